// round 17
// baseline (speedup 1.0000x reference)
#include <cuda_runtime.h>
#include <cuda_bf16.h>
#include <stdint.h>
#include <math.h>

#define NN 4096
#define DD 512
#define NBLK 32                     // 128-row blocks
#define NPAIR 528                   // NBLK*(NBLK+1)/2 upper-triangle tiles
#define NSLOT 32                    // partial slots per row (one per other-block)
#define KC 32                       // K elems per pipeline chunk
#define NCH (DD / KC)               // 16 chunks
#define NSTG 4                      // pipeline depth (buffers)

#define NEGBIG (-1e30f)
#define F_GAMMA 256.0f
#define F_OP 1.25f
#define F_ON (-0.25f)
#define F_DP 0.75f
#define F_DN 0.25f

// smem: [tcs 512B][pad][4 x 16KB stages]; stage = A(8K: 128 rows x 64B) B(8K)
#define OFF_STAGE 1024
#define STAGE_BYTES 16384
#define SMEM_TOTAL (OFF_STAGE + NSTG * STAGE_BYTES)   // 66560 -> 2 CTAs/SM

// ---------------- scratch ----------------
__device__ __nv_bfloat16 g_hi[NN * DD];
__device__ int   g_tg[NN];
__device__ float g_part[NN * NSLOT * 8];   // [row][slot][8] = 4 MB
__device__ float g_row[NN];
__device__ float g_val[NN];

// ---------------- PTX helpers (sm_80-level only) ----------------
__device__ __forceinline__ uint32_t smem_u32(const void* p) {
    uint32_t a;
    asm("{ .reg .u64 t; cvta.to.shared.u64 t, %1; cvt.u32.u64 %0, t; }" : "=r"(a) : "l"(p));
    return a;
}
__device__ __forceinline__ void cp16(uint32_t dst, const void* src) {
    asm volatile("cp.async.cg.shared.global [%0], [%1], 16;" :: "r"(dst), "l"(src) : "memory");
}
__device__ __forceinline__ void cp_commit() { asm volatile("cp.async.commit_group;" ::: "memory"); }
template<int N> __device__ __forceinline__ void cp_wait() {
    asm volatile("cp.async.wait_group %0;" :: "n"(N) : "memory");
}
__device__ __forceinline__ void ldsm4(uint32_t a[4], uint32_t addr) {
    asm volatile("ldmatrix.sync.aligned.m8n8.x4.shared.b16 {%0,%1,%2,%3}, [%4];"
        : "=r"(a[0]), "=r"(a[1]), "=r"(a[2]), "=r"(a[3]) : "r"(addr));
}
__device__ __forceinline__ void mma16816(float c[4], const uint32_t a[4], const uint32_t b[2]) {
    asm volatile("mma.sync.aligned.m16n8k16.row.col.f32.bf16.bf16.f32 "
        "{%0,%1,%2,%3}, {%4,%5,%6,%7}, {%8,%9}, {%0,%1,%2,%3};"
        : "+f"(c[0]), "+f"(c[1]), "+f"(c[2]), "+f"(c[3])
        : "r"(a[0]), "r"(a[1]), "r"(a[2]), "r"(a[3]), "r"(b[0]), "r"(b[1]));
}
// swizzle for 64-byte rows: q = 16B-unit (0..3), r = row index
__device__ __forceinline__ uint32_t sw64(int r, int q) {
    return (uint32_t)r * 64u + (uint32_t)((q ^ ((r >> 1) & 3)) << 4);
}

// ---------------- targets dtype-detect ----------------
__global__ void ck_tgt(const void* tptr) {
    const int* p32 = (const int*)tptr;
    int lf = 1;
    for (int i = threadIdx.x; i < NN / 2; i += blockDim.x)
        if (p32[2 * i + 1] != 0) lf = 0;
    int is64 = __syncthreads_and(lf);
    const long long* p64 = (const long long*)tptr;
    for (int i = threadIdx.x; i < NN; i += blockDim.x)
        g_tg[i] = is64 ? (int)p64[i] : p32[i];
}

// ---------------- normalize -> bf16 ----------------
__global__ void ck_norm(const float* __restrict__ x) {
    int row = blockIdx.x;
    int t = threadIdx.x;                 // 128
    const float* r = x + row * DD;
    float v[4];
    float s = 0.f;
#pragma unroll
    for (int i = 0; i < 4; i++) { v[i] = r[t + 128 * i]; s += v[i] * v[i]; }
#pragma unroll
    for (int o = 16; o > 0; o >>= 1) s += __shfl_down_sync(0xffffffffu, s, o);
    __shared__ float red[4];
    if ((t & 31) == 0) red[t >> 5] = s;
    __syncthreads();
    if (t == 0) red[0] = red[0] + red[1] + red[2] + red[3];
    __syncthreads();
    float inv = 1.0f / sqrtf(red[0]);
#pragma unroll
    for (int i = 0; i < 4; i++)
        g_hi[row * DD + t + 128 * i] = __float2bfloat16(v[i] * inv);
}

// ---------------- online-lse helpers ----------------
__device__ __forceinline__ void lse_add(float& m, float& s, float term) {
    if (term > m) { s = s * __expf(m - term) + 1.f; m = term; }
    else          { s += __expf(term - m); }
}
__device__ __forceinline__ void lse_merge(float& m, float& s, float om, float os) {
    float M = fmaxf(m, om);
    s = s * __expf(m - M) + os * __expf(om - M);
    m = M;
}

// ---------------- symmetric mma.sync GEMM (bf16, upper triangle) ----------------
__global__ void __launch_bounds__(256, 2) ck_main() {
    extern __shared__ char smem[];
    const int tid = threadIdx.x;
    const int wid = tid >> 5, lane = tid & 31;
    const int wm = wid & 1, wn = wid >> 1;        // warp tile: rows wm*64, cols wn*32

    // decode upper-triangle pair (I <= J)
    int p = blockIdx.x, I = 0;
    while (p >= NBLK - I) { p -= NBLK - I; I++; }
    const int J = I + p;
    const int rbI = I * 128, rbJ = J * 128;
    const bool diag = (I == J);

    const uint32_t sstage = smem_u32(smem) + OFF_STAGE;
    int* tcs = (int*)smem;                         // 128 ints: J-block targets
    if (tid < 128) tcs[tid] = g_tg[rbJ + tid];

    // staging geometry: lanes 0-3 cover one 64B row (4x16B), 8 rows per warp-instr
    const int s_q = lane & 3;
    const int s_r8 = lane >> 2;                    // 0..7 row within group
    // ldmatrix lane geometry
    const int l7 = lane & 7;
    const int m8 = (lane >> 3) & 1;                // A: row +8 select
    const int kA = lane >> 4;                      // A: k-half
    const int kB = (lane >> 3) & 1;                // B: k-half
    const int nB8 = (lane >> 4) & 1;               // B: n +8 select
    const int g4 = lane >> 2;

    float acc[4][4][4];
#pragma unroll
    for (int a = 0; a < 4; a++)
#pragma unroll
        for (int b = 0; b < 4; b++)
#pragma unroll
            for (int v = 0; v < 4; v++) acc[a][b][v] = 0.f;

    // stage one K-chunk (A: 128 I-rows, B: 128 J-rows, 64B each) -> 16KB
    auto stage = [&](int c, int buf) {
        const uint32_t sbase = sstage + (uint32_t)buf * STAGE_BYTES;
#pragma unroll
        for (int j = 0; j < 4; j++) {
            int inst = wid * 32 + j * 8 + s_r8;    // 0..255 row-instances
            int mtx = inst >> 7;                   // 0 A, 1 B
            int r = inst & 127;
            int grow = (mtx ? rbJ : rbI) + r;
            const __nv_bfloat16* src = g_hi + (size_t)grow * DD + c * KC + s_q * 8;
            cp16(sbase + (uint32_t)(mtx * 8192) + sw64(r, s_q), src);
        }
        cp_commit();
    };

    auto mma_chunk = [&](int buf) {
        const uint32_t abase = sstage + (uint32_t)buf * STAGE_BYTES;
        const uint32_t bbase = abase + 8192u;
#pragma unroll
        for (int ks = 0; ks < 2; ks++) {           // 2 k16-steps per 32-chunk
            uint32_t bf[2][4];                     // [pair][4 regs: nf even b0,b1, nf odd b0,b1]
#pragma unroll
            for (int pr = 0; pr < 2; pr++) {
                int rB = wn * 32 + pr * 16 + nB8 * 8 + l7;
                ldsm4(bf[pr], bbase + sw64(rB, ks * 2 + kB));
            }
#pragma unroll
            for (int mf = 0; mf < 4; mf++) {
                int rA = wm * 64 + mf * 16 + m8 * 8 + l7;
                uint32_t ah[4];
                ldsm4(ah, abase + sw64(rA, ks * 2 + kA));
#pragma unroll
                for (int pr = 0; pr < 2; pr++) {
                    mma16816(acc[mf][pr * 2 + 0], ah, &bf[pr][0]);
                    mma16816(acc[mf][pr * 2 + 1], ah, &bf[pr][2]);
                }
            }
        }
    };

    // 4-deep pipeline, prefetch distance 3, ONE barrier per chunk
    stage(0, 0); stage(1, 1); stage(2, 2);
    for (int c = 0; c < NCH; c++) {
        if (c < NCH - 2)      cp_wait<2>();
        else if (c == NCH - 2) cp_wait<1>();
        else                  cp_wait<0>();
        __syncthreads();      // publishes chunk c; guards buffer reuse for stage(c+3)
        if (c + 3 < NCH) stage(c + 3, (c + 3) & (NSTG - 1));
        mma_chunk(c & (NSTG - 1));
    }

    // ---- epilogue pass geometry ----
    int rloc[8], trow[8];
#pragma unroll
    for (int i = 0; i < 8; i++) {
        rloc[i] = wm * 64 + (i >> 1) * 16 + (i & 1) * 8 + g4;
        trow[i] = g_tg[rbI + rloc[i]];
    }
    int cloc[8], tcol[8];
#pragma unroll
    for (int j = 0; j < 8; j++) {
        cloc[j] = wn * 32 + (j >> 1) * 8 + (lane & 3) * 2 + (j & 1);
        tcol[j] = tcs[cloc[j]];
    }

    float* rred = (float*)(smem + OFF_STAGE);            // [128 rows][4 wn][8]
    float* cred = (float*)(smem + OFF_STAGE + 16384);    // [128 cols][2 wm][8]

    // ---- pass 1: row-side state only (keeps live regs < 128, no spills) ----
    {
        float rm_p[8], rs_p[8], rmnp[8], rcnt[8], rm_n[8], rs_n[8], rmxn[8];
#pragma unroll
        for (int i = 0; i < 8; i++) {
            rm_p[i] = NEGBIG; rs_p[i] = 0.f; rmnp[i] = 2.f; rcnt[i] = 0.f;
            rm_n[i] = NEGBIG; rs_n[i] = 0.f; rmxn[i] = -2.f;
        }
#pragma unroll
        for (int mf = 0; mf < 4; mf++)
#pragma unroll
            for (int nf = 0; nf < 4; nf++)
#pragma unroll
                for (int v = 0; v < 4; v++) {
                    int idx = mf * 2 + (v >> 1);
                    int jdx = nf * 2 + (v & 1);
                    float sv = acc[mf][nf][v];
                    if (tcol[jdx] == trow[idx]) {
                        if (!diag || (rloc[idx] != cloc[jdx])) {
                            rcnt[idx] += 1.f; rmnp[idx] = fminf(rmnp[idx], sv);
                            lse_add(rm_p[idx], rs_p[idx],
                                    -F_GAMMA * fmaxf(0.f, F_OP - sv) * (sv - F_DP));
                        }
                    } else {
                        rmxn[idx] = fmaxf(rmxn[idx], sv);
                        lse_add(rm_n[idx], rs_n[idx],
                                F_GAMMA * fmaxf(0.f, sv - F_ON) * (sv - F_DN));
                    }
                }
#pragma unroll
        for (int i = 0; i < 8; i++)
#pragma unroll
            for (int o = 1; o <= 2; o <<= 1) {
                lse_merge(rm_p[i], rs_p[i], __shfl_xor_sync(0xffffffffu, rm_p[i], o),
                                            __shfl_xor_sync(0xffffffffu, rs_p[i], o));
                lse_merge(rm_n[i], rs_n[i], __shfl_xor_sync(0xffffffffu, rm_n[i], o),
                                            __shfl_xor_sync(0xffffffffu, rs_n[i], o));
                rmnp[i] = fminf(rmnp[i], __shfl_xor_sync(0xffffffffu, rmnp[i], o));
                rmxn[i] = fmaxf(rmxn[i], __shfl_xor_sync(0xffffffffu, rmxn[i], o));
                rcnt[i] += __shfl_xor_sync(0xffffffffu, rcnt[i], o);
            }
        if ((lane & 3) == 0) {
#pragma unroll
            for (int i = 0; i < 8; i++) {
                float* q = rred + ((size_t)rloc[i] * 4 + wn) * 8;
                q[0] = rm_p[i]; q[1] = rs_p[i]; q[2] = rmnp[i]; q[3] = rcnt[i];
                q[4] = rm_n[i]; q[5] = rs_n[i]; q[6] = rmxn[i];
            }
        }
    }

    // ---- pass 2: col-side state only ----
    {
        float cm_p[8], cs_p[8], cmnp[8], ccnt[8], cm_n[8], cs_n[8], cmxn[8];
#pragma unroll
        for (int j = 0; j < 8; j++) {
            cm_p[j] = NEGBIG; cs_p[j] = 0.f; cmnp[j] = 2.f; ccnt[j] = 0.f;
            cm_n[j] = NEGBIG; cs_n[j] = 0.f; cmxn[j] = -2.f;
        }
#pragma unroll
        for (int mf = 0; mf < 4; mf++)
#pragma unroll
            for (int nf = 0; nf < 4; nf++)
#pragma unroll
                for (int v = 0; v < 4; v++) {
                    int idx = mf * 2 + (v >> 1);
                    int jdx = nf * 2 + (v & 1);
                    float sv = acc[mf][nf][v];
                    if (tcol[jdx] == trow[idx]) {
                        if (!diag || (rloc[idx] != cloc[jdx])) {
                            ccnt[jdx] += 1.f; cmnp[jdx] = fminf(cmnp[jdx], sv);
                            lse_add(cm_p[jdx], cs_p[jdx],
                                    -F_GAMMA * fmaxf(0.f, F_OP - sv) * (sv - F_DP));
                        }
                    } else {
                        cmxn[jdx] = fmaxf(cmxn[jdx], sv);
                        lse_add(cm_n[jdx], cs_n[jdx],
                                F_GAMMA * fmaxf(0.f, sv - F_ON) * (sv - F_DN));
                    }
                }
#pragma unroll
        for (int j = 0; j < 8; j++)
#pragma unroll
            for (int o = 4; o <= 16; o <<= 1) {
                lse_merge(cm_p[j], cs_p[j], __shfl_xor_sync(0xffffffffu, cm_p[j], o),
                                            __shfl_xor_sync(0xffffffffu, cs_p[j], o));
                lse_merge(cm_n[j], cs_n[j], __shfl_xor_sync(0xffffffffu, cm_n[j], o),
                                            __shfl_xor_sync(0xffffffffu, cs_n[j], o));
                cmnp[j] = fminf(cmnp[j], __shfl_xor_sync(0xffffffffu, cmnp[j], o));
                cmxn[j] = fmaxf(cmxn[j], __shfl_xor_sync(0xffffffffu, cmxn[j], o));
                ccnt[j] += __shfl_xor_sync(0xffffffffu, ccnt[j], o);
            }
        if (lane < 4) {
#pragma unroll
            for (int j = 0; j < 8; j++) {
                float* q = cred + ((size_t)cloc[j] * 2 + wm) * 8;
                q[0] = cm_p[j]; q[1] = cs_p[j]; q[2] = cmnp[j]; q[3] = ccnt[j];
                q[4] = cm_n[j]; q[5] = cs_n[j]; q[6] = cmxn[j];
            }
        }
    }
    __syncthreads();

    if (tid < 128) {                 // merge 4 row-partials -> g_part[rbI+tid][J]
        float mp = NEGBIG, sp = 0.f, mn2 = 2.f, ct = 0.f, mnn = NEGBIG, snn = 0.f, mx2 = -2.f;
#pragma unroll
        for (int s = 0; s < 4; s++) {
            const float* q = rred + ((size_t)tid * 4 + s) * 8;
            lse_merge(mp, sp, q[0], q[1]);
            mn2 = fminf(mn2, q[2]); ct += q[3];
            lse_merge(mnn, snn, q[4], q[5]);
            mx2 = fmaxf(mx2, q[6]);
        }
        float* gp = &g_part[(size_t)((rbI + tid) * NSLOT + J) * 8];
        gp[0] = mp; gp[1] = sp; gp[2] = mn2; gp[3] = ct;
        gp[4] = mnn; gp[5] = snn; gp[6] = mx2;
    } else if (!diag) {              // merge 2 col-partials -> g_part[rbJ+c][I]
        int c = tid - 128;
        float mp = NEGBIG, sp = 0.f, mn2 = 2.f, ct = 0.f, mnn = NEGBIG, snn = 0.f, mx2 = -2.f;
#pragma unroll
        for (int s = 0; s < 2; s++) {
            const float* q = cred + ((size_t)c * 2 + s) * 8;
            lse_merge(mp, sp, q[0], q[1]);
            mn2 = fminf(mn2, q[2]); ct += q[3];
            lse_merge(mnn, snn, q[4], q[5]);
            mx2 = fmaxf(mx2, q[6]);
        }
        float* gp = &g_part[(size_t)((rbJ + c) * NSLOT + I) * 8];
        gp[0] = mp; gp[1] = sp; gp[2] = mn2; gp[3] = ct;
        gp[4] = mnn; gp[5] = snn; gp[6] = mx2;
    }
}

// ---------------- per-row finalize: warp per row, lane = slot ----------------
__global__ void ck_final() {
    int r = (blockIdx.x * blockDim.x + threadIdx.x) >> 5;
    int lane = threadIdx.x & 31;
    if (r >= NN) return;
    const float* p = &g_part[(size_t)(r * NSLOT + lane) * 8];
    float m_p = p[0], s_p = p[1], mnp = p[2], cnt = p[3];
    float m_n = p[4], s_n = p[5], mxn = p[6];
#pragma unroll
    for (int o = 16; o > 0; o >>= 1) {
        lse_merge(m_p, s_p, __shfl_xor_sync(0xffffffffu, m_p, o),
                            __shfl_xor_sync(0xffffffffu, s_p, o));
        lse_merge(m_n, s_n, __shfl_xor_sync(0xffffffffu, m_n, o),
                            __shfl_xor_sync(0xffffffffu, s_n, o));
        mnp = fminf(mnp, __shfl_xor_sync(0xffffffffu, mnp, o));
        mxn = fmaxf(mxn, __shfl_xor_sync(0xffffffffu, mxn, o));
        cnt += __shfl_xor_sync(0xffffffffu, cnt, o);
    }
    if (lane == 0) {
        float npos = cnt;
        float nneg = (float)(NN - 1) - npos;
        float loss = 0.f, val = 0.f;
        if (npos > 0.5f && nneg > 0.5f) {
            float lse_p, lse_n;
            {
                float th = -F_GAMMA * fmaxf(0.f, F_OP - mnp) * (mnp - F_DP);
                if (npos > 1.5f) {
                    float M = fmaxf(m_p, 2.f * th);
                    float S = s_p * expf(m_p - M) - expf(th - M) + expf(2.f * th - M);
                    lse_p = M + logf(fmaxf(S, 1e-37f));
                } else lse_p = m_p + logf(s_p);
            }
            {
                float tn = F_GAMMA * fmaxf(0.f, mxn - F_ON) * (mxn - F_DN);
                if (nneg > 1.5f) {
                    float M = fmaxf(m_n, 2.f * tn);
                    float S = s_n * expf(m_n - M) - expf(tn - M) + expf(2.f * tn - M);
                    lse_n = M + logf(fmaxf(S, 1e-37f));
                } else lse_n = m_n + logf(s_n);
            }
            float z = lse_p + lse_n;
            loss = fmaxf(z, 0.f) + log1pf(expf(-fabsf(z)));
            val = 1.f;
        }
        g_row[r] = loss;
        g_val[r] = val;
    }
}

// ---------------- deterministic scalar reduction ----------------
__global__ void ck_reduce(float* __restrict__ out) {
    int t = threadIdx.x;  // 512
    float s = 0.f, v = 0.f;
    for (int i = t; i < NN; i += 512) { s += g_row[i]; v += g_val[i]; }
#pragma unroll
    for (int o = 16; o > 0; o >>= 1) {
        s += __shfl_down_sync(0xffffffffu, s, o);
        v += __shfl_down_sync(0xffffffffu, v, o);
    }
    __shared__ float ss[16], vv[16];
    if ((t & 31) == 0) { ss[t >> 5] = s; vv[t >> 5] = v; }
    __syncthreads();
    if (t < 32) {
        s = (t < 16) ? ss[t] : 0.f;
        v = (t < 16) ? vv[t] : 0.f;
#pragma unroll
        for (int o = 8; o > 0; o >>= 1) {
            s += __shfl_down_sync(0xffffffffu, s, o);
            v += __shfl_down_sync(0xffffffffu, v, o);
        }
        if (t == 0) out[0] = s / fmaxf(v, 1.f);
    }
}

extern "C" void kernel_launch(void* const* d_in, const int* in_sizes, int n_in,
                              void* d_out, int out_size) {
    const float* x = (const float*)d_in[0];
    const void* tg = d_in[1];
    float* out = (float*)d_out;
    (void)in_sizes; (void)n_in; (void)out_size;

    cudaFuncSetAttribute(ck_main, cudaFuncAttributeMaxDynamicSharedMemorySize, SMEM_TOTAL);

    ck_tgt<<<1, 256>>>(tg);
    ck_norm<<<NN, 128>>>(x);
    ck_main<<<NPAIR, 256, SMEM_TOTAL>>>();
    ck_final<<<NN / 8, 256>>>();
    ck_reduce<<<1, 512>>>(out);
}